// round 7
// baseline (speedup 1.0000x reference)
#include <cuda_runtime.h>
#include <cstdint>

#define T_TOK 8192
#define MDIM  1024
#define NEXP  8
#define DFFD  4096
#define CAP   1280

// ---------------- device scratch ----------------
__device__ __align__(256) float g_disp[(size_t)NEXP * CAP * MDIM];   //  41.9 MB (tf32-rounded)
__device__ __align__(256) float g_h   [(size_t)NEXP * CAP * DFFD];   // 167.8 MB (tf32-rounded)
__device__ __align__(256) float g_oute[(size_t)NEXP * CAP * MDIM];   //  41.9 MB
__device__ int   g_expert[T_TOK];
__device__ float g_gate[T_TOK];
__device__ int   g_slot[T_TOK];

// ---------------- helpers ----------------
__device__ __forceinline__ uint32_t smem_u32(const void* p) {
    uint32_t a;
    asm("{ .reg .u64 t; cvta.to.shared.u64 t, %1; cvt.u32.u64 %0, t; }" : "=r"(a) : "l"(p));
    return a;
}
__device__ __forceinline__ float tf32r(float v) {
    uint32_t u;
    asm("cvt.rna.tf32.f32 %0, %1;" : "=r"(u) : "f"(v));
    return __uint_as_float(u);
}
__device__ __forceinline__ uint32_t tf32u(float v) {
    uint32_t u;
    asm("cvt.rna.tf32.f32 %0, %1;" : "=r"(u) : "f"(v));
    return u;
}

#define CPASYNC16(dst, src) \
    asm volatile("cp.async.cg.shared.global [%0], [%1], 16;" :: "r"(dst), "l"(src) : "memory")
#define CPCOMMIT()  asm volatile("cp.async.commit_group;" ::: "memory")
#define CPWAIT(n)   asm volatile("cp.async.wait_group %0;" :: "n"(n) : "memory")

// m16n8k8 tf32 mma
__device__ __forceinline__ void mma_tf32(float* d, const uint32_t* a, const uint32_t* b) {
    asm volatile(
        "mma.sync.aligned.m16n8k8.row.col.f32.tf32.tf32.f32 "
        "{%0,%1,%2,%3}, {%4,%5,%6,%7}, {%8,%9}, {%0,%1,%2,%3};"
        : "+f"(d[0]), "+f"(d[1]), "+f"(d[2]), "+f"(d[3])
        : "r"(a[0]), "r"(a[1]), "r"(a[2]), "r"(a[3]), "r"(b[0]), "r"(b[1]));
}

// ---------------- K1: gating ----------------
__global__ void gate_kernel(const float* __restrict__ x, const float* __restrict__ wg)
{
    int warp = (blockIdx.x * blockDim.x + threadIdx.x) >> 5;
    int lane = threadIdx.x & 31;
    if (warp >= T_TOK) return;

    const float* xr = x + (size_t)warp * MDIM;
    float acc[8] = {0.f,0.f,0.f,0.f,0.f,0.f,0.f,0.f};

    #pragma unroll 4
    for (int i = 0; i < MDIM / 32; i++) {
        int m = i * 32 + lane;
        float xv = __ldg(xr + m);
        const float4* w4 = reinterpret_cast<const float4*>(wg + (size_t)m * NEXP);
        float4 a = w4[0], b = w4[1];
        acc[0] += xv * a.x; acc[1] += xv * a.y;
        acc[2] += xv * a.z; acc[3] += xv * a.w;
        acc[4] += xv * b.x; acc[5] += xv * b.y;
        acc[6] += xv * b.z; acc[7] += xv * b.w;
    }
    #pragma unroll
    for (int e = 0; e < 8; e++)
        #pragma unroll
        for (int off = 16; off > 0; off >>= 1)
            acc[e] += __shfl_xor_sync(0xffffffffu, acc[e], off);

    if (lane == 0) {
        float mx = acc[0]; int bi = 0;
        #pragma unroll
        for (int e = 1; e < 8; e++)
            if (acc[e] > mx) { mx = acc[e]; bi = e; }
        float s = 0.f;
        #pragma unroll
        for (int e = 0; e < 8; e++) s += expf(acc[e] - mx);
        g_expert[warp] = bi;
        g_gate[warp]   = 1.0f / s;
    }
}

// ---------------- K2: ordered per-expert rank ----------------
__global__ void pos_kernel()
{
    __shared__ int hist[1024][8];
    int tid = threadIdx.x;
    int base_t = tid * 8;

    int cnt[8] = {0,0,0,0,0,0,0,0};
    int loc[8];
    #pragma unroll
    for (int i = 0; i < 8; i++) {
        int e = g_expert[base_t + i];
        loc[i] = e;
        cnt[e]++;
    }
    #pragma unroll
    for (int e = 0; e < 8; e++) hist[tid][e] = cnt[e];
    __syncthreads();

    for (int off = 1; off < 1024; off <<= 1) {
        int v[8];
        bool p = (tid >= off);
        if (p) {
            #pragma unroll
            for (int e = 0; e < 8; e++) v[e] = hist[tid - off][e];
        }
        __syncthreads();
        if (p) {
            #pragma unroll
            for (int e = 0; e < 8; e++) hist[tid][e] += v[e];
        }
        __syncthreads();
    }

    int run[8];
    #pragma unroll
    for (int e = 0; e < 8; e++) run[e] = hist[tid][e] - cnt[e];

    #pragma unroll
    for (int i = 0; i < 8; i++) {
        int e = loc[i];
        int p = run[e]++;
        g_slot[base_t + i] = (p < CAP) ? (e * CAP + p) : -1;
    }
}

// ---------------- K3: scatter (+ tf32 rounding) ----------------
__global__ void scatter_kernel(const float* __restrict__ x)
{
    int t = blockIdx.x;
    int s = g_slot[t];
    if (s < 0) return;
    float4 v = reinterpret_cast<const float4*>(x + (size_t)t * MDIM)[threadIdx.x];
    v.x = tf32r(v.x); v.y = tf32r(v.y); v.z = tf32r(v.z); v.w = tf32r(v.w);
    reinterpret_cast<float4*>(g_disp + (size_t)s * MDIM)[threadIdx.x] = v;
}

// ---------------- K4: tf32 mma.sync GEMM ----------------
// 128 threads, 4 warps (2x2), warp tile 64x64, CTA tile 128x128, BK=32.
// smem: As [128 rows][36], Bs [32 k-rows][132]; both conflict-free for frag reads.
#define A_ST 4608   // 128*36 floats per stage
#define B_ST 4224   // 32*132 floats per stage
#define GEMM_SMEM ((2 * A_ST + 2 * B_ST) * 4)   // 70656 bytes

template<bool RELU, bool CVT>
__global__ void __launch_bounds__(128, 2)
moe_gemm(const float* __restrict__ Ag, const float* __restrict__ Bg,
         const float* __restrict__ biasg, float* __restrict__ Cg,
         int Ndim, int Kdim)
{
    extern __shared__ float sm[];
    const uint32_t su = smem_u32(sm);
    const int tid = threadIdx.x;
    const int wid = tid >> 5, lane = tid & 31;
    const int g = lane >> 2, tg = lane & 3;
    const int wm = (wid >> 1) * 64;          // warp row base: 0 / 64
    const int wn = (wid & 1) * 64;           // warp col base: 0 / 64

    const int z = blockIdx.z;
    const float* A = Ag + (size_t)z * CAP * Kdim + (size_t)(blockIdx.y * 128) * Kdim;
    const float* B = Bg + (size_t)z * Kdim * Ndim + blockIdx.x * 128;
    const float* bias = biasg + (size_t)z * Ndim + blockIdx.x * 128;
    float* C = Cg + (size_t)z * CAP * Ndim + (size_t)(blockIdx.y * 128) * Ndim + blockIdx.x * 128;

    // loader assignments (128 threads)
    const int arow = tid;                         // A: 1 thr/row, 8x16B
    const int brow = tid >> 2, bseg = (tid & 3) * 4;  // B: 4 thr/row, 8x16B strided 64B

    float acc[4][8][4];
    #pragma unroll
    for (int i = 0; i < 4; i++)
        #pragma unroll
        for (int j = 0; j < 8; j++)
            #pragma unroll
            for (int q = 0; q < 4; q++) acc[i][j][q] = 0.f;

    auto load_stage = [&](int kt) {
        int s = kt & 1;
        const float* ag = A + (size_t)arow * Kdim + kt * 32;
        uint32_t ad = su + (uint32_t)(s * A_ST + arow * 36) * 4;
        #pragma unroll
        for (int i = 0; i < 8; i++)
            CPASYNC16(ad + i * 16, ag + i * 4);
        const float* bg = B + (size_t)(kt * 32 + brow) * Ndim + bseg;
        uint32_t bd = su + (uint32_t)(2 * A_ST + s * B_ST + brow * 132 + bseg) * 4;
        #pragma unroll
        for (int i = 0; i < 8; i++)
            CPASYNC16(bd + i * 64, bg + i * 16);   // +16 cols = +64 bytes
        CPCOMMIT();
    };

    load_stage(0);
    const int KT = Kdim >> 5;

    for (int kt = 0; kt < KT; kt++) {
        if (kt + 1 < KT) {
            load_stage(kt + 1);
            CPWAIT(1);
        } else {
            CPWAIT(0);
        }
        __syncthreads();

        const float* as = sm + (kt & 1) * A_ST;
        const float* bs = sm + 2 * A_ST + (kt & 1) * B_ST;

        #pragma unroll
        for (int ks = 0; ks < 4; ks++) {
            const int k0 = ks * 8;
            uint32_t afr[4][4], bfr[8][2];
            #pragma unroll
            for (int i = 0; i < 4; i++) {
                const float* ap = as + (wm + i * 16 + g) * 36 + k0 + tg;
                afr[i][0] = __float_as_uint(ap[0]);
                afr[i][1] = __float_as_uint(ap[8 * 36]);
                afr[i][2] = __float_as_uint(ap[4]);
                afr[i][3] = __float_as_uint(ap[8 * 36 + 4]);
            }
            #pragma unroll
            for (int j = 0; j < 8; j++) {
                const float* bp = bs + (k0 + tg) * 132 + wn + j * 8 + g;
                bfr[j][0] = tf32u(bp[0]);          // RNA-round weights to tf32
                bfr[j][1] = tf32u(bp[4 * 132]);
            }
            #pragma unroll
            for (int i = 0; i < 4; i++)
                #pragma unroll
                for (int j = 0; j < 8; j++)
                    mma_tf32(acc[i][j], afr[i], bfr[j]);
        }
        __syncthreads();
    }

    // epilogue
    #pragma unroll
    for (int j = 0; j < 8; j++) {
        const int col = wn + j * 8 + 2 * tg;
        float2 bv = *reinterpret_cast<const float2*>(bias + col);
        #pragma unroll
        for (int i = 0; i < 4; i++) {
            const int r0 = wm + i * 16 + g;
            float v00 = acc[i][j][0] + bv.x, v01 = acc[i][j][1] + bv.y;
            float v10 = acc[i][j][2] + bv.x, v11 = acc[i][j][3] + bv.y;
            if (RELU) {
                v00 = fmaxf(v00, 0.f); v01 = fmaxf(v01, 0.f);
                v10 = fmaxf(v10, 0.f); v11 = fmaxf(v11, 0.f);
            }
            if (CVT) {
                v00 = tf32r(v00); v01 = tf32r(v01);
                v10 = tf32r(v10); v11 = tf32r(v11);
            }
            *reinterpret_cast<float2*>(C + (size_t)r0 * Ndim + col) = make_float2(v00, v01);
            *reinterpret_cast<float2*>(C + (size_t)(r0 + 8) * Ndim + col) = make_float2(v10, v11);
        }
    }
}

// ---------------- K6: gather ----------------
__global__ void gather_kernel(float* __restrict__ out)
{
    int t = blockIdx.x;
    int s = g_slot[t];
    float4* dst = reinterpret_cast<float4*>(out + (size_t)t * MDIM);
    if (s < 0) {
        dst[threadIdx.x] = make_float4(0.f, 0.f, 0.f, 0.f);
        return;
    }
    float g = g_gate[t];
    float4 v = reinterpret_cast<const float4*>(g_oute + (size_t)s * MDIM)[threadIdx.x];
    dst[threadIdx.x] = make_float4(v.x * g, v.y * g, v.z * g, v.w * g);
}

// ---------------- launch ----------------
extern "C" void kernel_launch(void* const* d_in, const int* in_sizes, int n_in,
                              void* d_out, int out_size)
{
    const float* x  = (const float*)d_in[0];
    const float* wg = (const float*)d_in[1];
    const float* w1 = (const float*)d_in[2];   // [E, M, DFF]  B of GEMM1 ([k][n])
    const float* b1 = (const float*)d_in[3];
    const float* w2 = (const float*)d_in[4];   // [E, DFF, M]  B of GEMM2 ([k][n])
    const float* b2 = (const float*)d_in[5];
    float* out = (float*)d_out;

    float *disp, *h, *oute;
    cudaGetSymbolAddress((void**)&disp, g_disp);
    cudaGetSymbolAddress((void**)&h,    g_h);
    cudaGetSymbolAddress((void**)&oute, g_oute);

    cudaFuncSetAttribute(moe_gemm<true, true>,
                         cudaFuncAttributeMaxDynamicSharedMemorySize, GEMM_SMEM);
    cudaFuncSetAttribute(moe_gemm<false, false>,
                         cudaFuncAttributeMaxDynamicSharedMemorySize, GEMM_SMEM);

    gate_kernel<<<T_TOK / 8, 256>>>(x, wg);
    pos_kernel<<<1, 1024>>>();
    scatter_kernel<<<T_TOK, 256>>>(x);

    // GEMM1: h = relu(disp @ w1 + b1)   per-expert [1280,1024] x [1024,4096]
    moe_gemm<true, true><<<dim3(DFFD / 128, CAP / 128, NEXP), 128, GEMM_SMEM>>>(
        disp, w1, b1, h, DFFD, MDIM);

    // GEMM2: oute = h @ w2 + b2         per-expert [1280,4096] x [4096,1024]
    moe_gemm<false, false><<<dim3(MDIM / 128, CAP / 128, NEXP), 128, GEMM_SMEM>>>(
        h, w2, b2, oute, MDIM, DFFD);

    gather_kernel<<<T_TOK, 256>>>(out);
}